// round 14
// baseline (speedup 1.0000x reference)
#include <cuda_runtime.h>

#define B 64
#define N 1024
#define D 14
#define HDP 8          // head dim padded 7 -> 8
#define SEPS 1e-10f
#define NSLAB 32       // row-slabs per matrix (32 rows each)
#define GB 16          // batches per L2-resident group

// ---------------- device scratch (static globals: allowed) ----------------
__device__ float g_P0[(size_t)B * N * N];          // 256 MB: (avg_attn + eps)^10
__device__ float g_Q[B * 2 * N * HDP];
__device__ float g_K[B * 2 * N * HDP];
__device__ float g_V[B * 2 * N * HDP];
__device__ float g_r[B * N];
__device__ float g_c[2][B * N];                    // double-buffered scaling vector c
__device__ float g_vpart[2][(size_t)NSLAB * B * N]; // double-buffered col partials

// ---------------- helpers ----------------
__device__ __forceinline__ float dot8(float4 a, float4 b, float4 c, float4 d) {
    return fmaf(a.x, b.x, fmaf(a.y, b.y, fmaf(a.z, b.z, fmaf(a.w, b.w,
           fmaf(c.x, d.x, fmaf(c.y, d.y, fmaf(c.z, d.z, c.w * d.w)))))));
}
__device__ __forceinline__ float4 fma4(float s, float4 v, float4 acc) {
    acc.x = fmaf(s, v.x, acc.x); acc.y = fmaf(s, v.y, acc.y);
    acc.z = fmaf(s, v.z, acc.z); acc.w = fmaf(s, v.w, acc.w);
    return acc;
}
__device__ __forceinline__ float dot4(float4 a, float4 b) {
    return fmaf(a.x, b.x, fmaf(a.y, b.y, fmaf(a.z, b.z, a.w * b.w)));
}
__device__ __forceinline__ void barsync(int id, int cnt) {
    asm volatile("bar.sync %0, %1;" :: "r"(id), "r"(cnt) : "memory");
}
__device__ __forceinline__ float4 add4(float4 a, float4 b) {
    return make_float4(a.x + b.x, a.y + b.y, a.z + b.z, a.w + b.w);
}

// ---------------- kernel 1: QKV projection ----------------
__global__ void qkv_kernel(const float* __restrict__ x,
                           const float* __restrict__ Wq, const float* __restrict__ bq,
                           const float* __restrict__ Wk, const float* __restrict__ bk,
                           const float* __restrict__ Wv, const float* __restrict__ bv) {
    __shared__ float w[3 * 196 + 3 * 14];
    int tid = threadIdx.x;
    for (int k = tid; k < 196; k += blockDim.x) {
        w[k] = Wq[k]; w[196 + k] = Wk[k]; w[392 + k] = Wv[k];
    }
    if (tid < 14) { w[588 + tid] = bq[tid]; w[602 + tid] = bk[tid]; w[616 + tid] = bv[tid]; }
    __syncthreads();

    int t = blockIdx.x * blockDim.x + tid;
    int b = t >> 10, i = t & 1023;
    float xv[14];
#pragma unroll
    for (int f = 0; f < 14; f++) xv[f] = x[(size_t)t * 14 + f];

#pragma unroll
    for (int e = 0; e < 14; e++) {
        float q = w[588 + e], k = w[602 + e], v = w[616 + e];
#pragma unroll
        for (int f = 0; f < 14; f++) {
            q = fmaf(w[e * 14 + f],       xv[f], q);
            k = fmaf(w[196 + e * 14 + f], xv[f], k);
            v = fmaf(w[392 + e * 14 + f], xv[f], v);
        }
        int h = e / 7, eh = e - h * 7;
        size_t idx = (((size_t)b * 2 + h) * N + i) * HDP + eh;
        g_Q[idx] = q; g_K[idx] = k; g_V[idx] = v;
    }
#pragma unroll
    for (int h = 0; h < 2; h++) {
        size_t idx = (((size_t)b * 2 + h) * N + i) * HDP + 7;
        g_Q[idx] = 0.f; g_K[idx] = 0.f; g_V[idx] = 0.f;
    }
}

// ---------------- kernel 2: fused attention (split-head, log2 domain) ----------------
// grid (8, GB), block 256 = 4 pairs x 2 head-warps. One thread = one (query, head).
__global__ __launch_bounds__(256) void attn_kernel(const float* __restrict__ cert,
                                                   const float* __restrict__ Wo,
                                                   const float* __restrict__ bo,
                                                   float* __restrict__ out,
                                                   float* __restrict__ out_cert,
                                                   int b0) {
    __shared__ float sWo[196];
    __shared__ float sbo[16];
    __shared__ float ph[4][2][32][33];

    int tid = threadIdx.x, w = tid >> 5, lane = tid & 31;
    int pair = w >> 1, h = w & 1;
    for (int k = tid; k < 196; k += 256) sWo[k] = Wo[k];
    if (tid < 14) sbo[tid] = bo[tid];
    __syncthreads();

    int b = b0 + blockIdx.y;
    int q = blockIdx.x * 128 + pair * 32 + lane;

    const float4* Kh = (const float4*)(g_K + ((size_t)b * 2 + h) * 8192);
    const float4* Vh = (const float4*)(g_V + ((size_t)b * 2 + h) * 8192);
    const float4* Qh = (const float4*)(g_Q + ((size_t)b * 2 + h) * 8192);

    const float sc = rsqrtf(7.0f) * 1.4426950408889634f;
    float4 qa = Qh[2 * q], qb = Qh[2 * q + 1];
    qa.x *= sc; qa.y *= sc; qa.z *= sc; qa.w *= sc;
    qb.x *= sc; qb.y *= sc; qb.z *= sc; qb.w *= sc;

    float Z = 0.f;
#pragma unroll 4
    for (int j = 0; j < 1024; j++)
        Z += exp2f(dot8(qa, Kh[2 * j], qb, Kh[2 * j + 1]));
    float inv = 1.f / Z;

    float4 va = make_float4(0.f, 0.f, 0.f, 0.f), vb = va;
    float ent2 = 0.f;
    size_t prow_base = ((size_t)b * N + (size_t)blockIdx.x * 128 + pair * 32) * N;
    const int bar = 1 + pair;

    for (int jc = 0; jc < 1024; jc += 32) {
#pragma unroll 4
        for (int jj = 0; jj < 32; jj++) {
            int j = jc + jj;
            float p = exp2f(dot8(qa, Kh[2 * j], qb, Kh[2 * j + 1])) * inv;
            ph[pair][h][lane][jj] = p;
            va = fma4(p, Vh[2 * j], va);
            vb = fma4(p, Vh[2 * j + 1], vb);
        }
        barsync(bar, 64);
#pragma unroll
        for (int k = 0; k < 16; k++) {
            int jj = h * 16 + k;
            float p0 = ph[pair][0][lane][jj];
            float p1 = ph[pair][1][lane][jj];
            float a = 0.5f * (p0 + p1);
            float t = a + SEPS;
            ent2 -= a * __log2f(t);
            float t2 = t * t, t4 = t2 * t2;
            ph[pair][0][lane][jj] = t4 * t4 * t2;
        }
        barsync(bar, 64);
#pragma unroll
        for (int r2 = 0; r2 < 16; r2++) {
            int r = h * 16 + r2;
            g_P0[prow_base + (size_t)r * N + jc + lane] = ph[pair][0][r][lane];
        }
        barsync(bar, 64);
    }

    float* xch = &ph[pair][1][lane][0];
    if (h == 1) {
        xch[0] = va.x; xch[1] = va.y; xch[2] = va.z; xch[3] = va.w;
        xch[4] = vb.x; xch[5] = vb.y; xch[6] = vb.z;
        xch[8] = ent2;
    }
    barsync(bar, 64);
    if (h == 0) {
        float pre[14] = {va.x, va.y, va.z, va.w, vb.x, vb.y, vb.z,
                         xch[0], xch[1], xch[2], xch[3], xch[4], xch[5], xch[6]};
        float* orow = out + ((size_t)b * N + q) * 14;
#pragma unroll
        for (int e = 0; e < 14; e++) {
            float o = sbo[e];
#pragma unroll
            for (int f = 0; f < 14; f++) o = fmaf(sWo[e * 14 + f], pre[f], o);
            orow[e] = o;
        }
        float entf = (ent2 + xch[8]) * 0.69314718056f;
        float cu = 1.f / (1.f + __expf(entf - 6.9314718f));
        out_cert[b * N + q] = fmaxf(cert[b * N + q], cu);
    }
}

// ---------------- Sinkhorn: fused c-update + row pass + col pass ----------------
// MODE 0 (t=1): c = 1, no c-compute. MODE 1 (t=2): c-compute with c_prev = 1.
// MODE 2 (t>=3): full. Each block recomputes c identically (deterministic) from
// vpart[vr] (+ c[cr]); block x==0 persists it to c[cw]. Then: u_i = row_i . c,
// r_i <- r_i/(r_i u_i + eps), vpart[vw] slab = sum_i r'_i P0_ij.
// grid (NSLAB=32, GB), block 512. Slab = 32 rows. part = even/odd row interleave.
template<int MODE>
__global__ __launch_bounds__(512) void sink_fused_kernel(int b0, int vr, int vw,
                                                         int cr, int cw) {
    __shared__ float4 sv[2][256];
    __shared__ float4 scm[256];
    __shared__ float su[32][8];
    __shared__ float sr[32];

    int b = b0 + blockIdx.y, s = blockIdx.x;
    int tid = threadIdx.x;
    int t8 = tid & 255, part = tid >> 8;
    int w = tid >> 5, lane = tid & 31;

    // phase 0: compute c for this iteration (all blocks identically)
    if (MODE >= 1) {
        const float4* vp = (const float4*)g_vpart[vr];
        float4 acc = make_float4(0.f, 0.f, 0.f, 0.f);
#pragma unroll
        for (int k = 0; k < 16; k++) {
            int sl = part * 16 + k;
            acc = add4(acc, vp[((size_t)sl * B + b) * 256 + t8]);
        }
        sv[part][t8] = acc;
        __syncthreads();
        if (part == 0) {
            float4 v = add4(sv[0][t8], sv[1][t8]);
            float4 c = (MODE == 1) ? make_float4(1.f, 1.f, 1.f, 1.f)
                                   : ((const float4*)(g_c[cr] + b * 1024))[t8];
            c.x = c.x / fmaf(c.x, v.x, SEPS);
            c.y = c.y / fmaf(c.y, v.y, SEPS);
            c.z = c.z / fmaf(c.z, v.z, SEPS);
            c.w = c.w / fmaf(c.w, v.w, SEPS);
            scm[t8] = c;
            if (s == 0) ((float4*)(g_c[cw] + b * 1024))[t8] = c;
        }
        __syncthreads();
    } else {
        if (part == 0) scm[t8] = make_float4(1.f, 1.f, 1.f, 1.f);
        __syncthreads();
    }
    float4 c4 = scm[t8];

    const float4* base = (const float4*)(g_P0 + ((size_t)b * N + (size_t)s * 32) * N);

    // phase A: row dots; thread covers rows part+2k at col-chunk t8
    float t[16];
#pragma unroll
    for (int k = 0; k < 16; k++)
        t[k] = dot4(base[(size_t)(part + 2 * k) * 256 + t8], c4);
#pragma unroll
    for (int k = 0; k < 16; k++) {
        float acc = t[k];
#pragma unroll
        for (int off = 16; off; off >>= 1) acc += __shfl_xor_sync(0xffffffffu, acc, off);
        if (lane == 0) su[part + 2 * k][w & 7] = acc;
    }
    __syncthreads();
    if (tid < 32) {
        float u = 0.f;
#pragma unroll
        for (int k = 0; k < 8; k++) u += su[tid][k];
        int ri = b * 1024 + s * 32 + tid;
        float r = (MODE == 0) ? 1.f : g_r[ri];
        r = r / fmaf(r, u, SEPS);
        g_r[ri] = r;
        sr[tid] = r;
    }
    __syncthreads();

    // phase B: column partials with updated r (reloads hit L1/L2; group is L2-hot)
    float4 v = make_float4(0.f, 0.f, 0.f, 0.f);
#pragma unroll
    for (int k = 0; k < 16; k++)
        v = fma4(sr[part + 2 * k], base[(size_t)(part + 2 * k) * 256 + t8], v);
    sv[part][t8] = v;
    __syncthreads();
    if (part == 0) {
        float4 o = add4(sv[0][t8], sv[1][t8]);
        ((float4*)(g_vpart[vw]))[((size_t)s * B + b) * 256 + t8] = o;
    }
}

// final per group: compute c_20 in-block, argmax_j P0_ij * c_j, gather permutation.
// grid (16, GB), block 512: 64 rows per block, warp w handles 4 rows.
__global__ __launch_bounds__(512) void sink_argmax_kernel(const int* __restrict__ perm,
                                                          float* __restrict__ out_perm,
                                                          int b0, int vr, int cr) {
    __shared__ float4 sv[2][256];
    __shared__ float4 scm[256];

    int b = b0 + blockIdx.y;
    int tid = threadIdx.x;
    int t8 = tid & 255, part = tid >> 8;
    int w = tid >> 5, lane = tid & 31;

    // compute final c (same math/order as sink_fused phase 0, MODE 2)
    {
        const float4* vp = (const float4*)g_vpart[vr];
        float4 acc = make_float4(0.f, 0.f, 0.f, 0.f);
#pragma unroll
        for (int k = 0; k < 16; k++) {
            int sl = part * 16 + k;
            acc = add4(acc, vp[((size_t)sl * B + b) * 256 + t8]);
        }
        sv[part][t8] = acc;
        __syncthreads();
        if (part == 0) {
            float4 v = add4(sv[0][t8], sv[1][t8]);
            float4 c = ((const float4*)(g_c[cr] + b * 1024))[t8];
            c.x = c.x / fmaf(c.x, v.x, SEPS);
            c.y = c.y / fmaf(c.y, v.y, SEPS);
            c.z = c.z / fmaf(c.z, v.z, SEPS);
            c.w = c.w / fmaf(c.w, v.w, SEPS);
            scm[t8] = c;
        }
        __syncthreads();
    }
    const float4* c4s = scm;

    // argmax: warp w owns rows i0 + 4w .. i0 + 4w + 3
    int i0 = blockIdx.x * 64;
#pragma unroll
    for (int rr = 0; rr < 4; rr++) {
        int i = i0 + w * 4 + rr;
        const float4* row4 = (const float4*)(g_P0 + ((size_t)b * N + i) * N);
        float best = -1.f; int bi = 1024;
#pragma unroll
        for (int k = 0; k < 8; k++) {
            int j4 = lane + 32 * k;
            float4 p = row4[j4], c = c4s[j4];
            float v0 = p.x * c.x, v1 = p.y * c.y, v2 = p.z * c.z, v3 = p.w * c.w;
            if (v0 > best) { best = v0; bi = 4 * j4; }
            if (v1 > best) { best = v1; bi = 4 * j4 + 1; }
            if (v2 > best) { best = v2; bi = 4 * j4 + 2; }
            if (v3 > best) { best = v3; bi = 4 * j4 + 3; }
        }
#pragma unroll
        for (int off = 16; off; off >>= 1) {
            float ov = __shfl_xor_sync(0xffffffffu, best, off);
            int   oi = __shfl_xor_sync(0xffffffffu, bi, off);
            if (ov > best || (ov == best && oi < bi)) { best = ov; bi = oi; }
        }
        if (lane == 0) out_perm[b * 1024 + i] = (float)perm[b * 1024 + bi];
    }
}

// ---------------- launch ----------------
extern "C" void kernel_launch(void* const* d_in, const int* in_sizes, int n_in,
                              void* d_out, int out_size) {
    const float* x    = (const float*)d_in[0];
    const float* cert = (const float*)d_in[1];
    const int*   perm = (const int*)d_in[2];
    const float* Wq = (const float*)d_in[3];  const float* bq = (const float*)d_in[4];
    const float* Wk = (const float*)d_in[5];  const float* bk = (const float*)d_in[6];
    const float* Wv = (const float*)d_in[7];  const float* bv = (const float*)d_in[8];
    const float* Wo = (const float*)d_in[9];  const float* bo = (const float*)d_in[10];

    float* out      = (float*)d_out;                       // (b,n,14)
    float* out_cert = out + (size_t)B * N * D;             // (b,n)
    float* out_perm = out_cert + (size_t)B * N;            // (b,n) as float

    qkv_kernel<<<256, 256>>>(x, Wq, bq, Wk, bk, Wv, bv);

    // per L2-resident batch group: attention -> 20 Sinkhorn iterations -> argmax
    for (int g = 0; g < B / GB; g++) {
        int b0 = g * GB;
        attn_kernel<<<dim3(8, GB), 256>>>(cert, Wo, bo, out, out_cert, b0);

        // t=1: c=1, write vpart[1]
        sink_fused_kernel<0><<<dim3(NSLAB, GB), 512>>>(b0, 0, 1, 0, 0);
        // t=2: c_1 from vpart[1] (c_0=1), write c[1], vpart[0]
        sink_fused_kernel<1><<<dim3(NSLAB, GB), 512>>>(b0, 1, 0, 0, 1);
        // t=3..20: c_{t-1} from vpart[(t-1)&1] + c[t&1], write c[(t-1)&1], vpart[t&1]
        for (int t = 3; t <= 20; t++) {
            sink_fused_kernel<2><<<dim3(NSLAB, GB), 512>>>(
                b0, (t - 1) & 1, t & 1, t & 1, (t - 1) & 1);
        }
        // final: c_20 from vpart[0] + c[1]; argmax over P0 * c_20
        sink_argmax_kernel<<<dim3(16, GB), 512>>>(perm, out_perm, b0, 0, 1);
    }
}

// round 15
// speedup vs baseline: 1.5392x; 1.5392x over previous
#include <cuda_runtime.h>

#define B 64
#define N 1024
#define D 14
#define HDP 8          // head dim padded 7 -> 8
#define SEPS 1e-10f
#define NSLAB 64       // row-slabs per matrix in fused sinkhorn (16 rows each)

// ---------------- device scratch (static globals: allowed) ----------------
__device__ float g_P0[(size_t)B * N * N];        // 256 MB: (avg_attn + eps)^10
__device__ float g_Q[B * 2 * N * HDP];           // (b,h,n,8)
__device__ float g_K[B * 2 * N * HDP];
__device__ float g_V[B * 2 * N * HDP];
__device__ float g_r[B * N];
__device__ float g_c[B * N];
__device__ float g_vpart[(size_t)NSLAB * B * N]; // deterministic col-sum partials (16.8 MB)
__device__ int   g_ctr[B];                       // per-batch completion counters (stay 0)

// ---------------- helpers ----------------
__device__ __forceinline__ float dot8(float4 a, float4 b, float4 c, float4 d) {
    return fmaf(a.x, b.x, fmaf(a.y, b.y, fmaf(a.z, b.z, fmaf(a.w, b.w,
           fmaf(c.x, d.x, fmaf(c.y, d.y, fmaf(c.z, d.z, c.w * d.w)))))));
}
__device__ __forceinline__ float4 fma4(float s, float4 v, float4 acc) {
    acc.x = fmaf(s, v.x, acc.x); acc.y = fmaf(s, v.y, acc.y);
    acc.z = fmaf(s, v.z, acc.z); acc.w = fmaf(s, v.w, acc.w);
    return acc;
}
__device__ __forceinline__ float dot4(float4 a, float4 b) {
    return fmaf(a.x, b.x, fmaf(a.y, b.y, fmaf(a.z, b.z, a.w * b.w)));
}
__device__ __forceinline__ float4 add4(float4 a, float4 b) {
    return make_float4(a.x + b.x, a.y + b.y, a.z + b.z, a.w + b.w);
}
__device__ __forceinline__ void barsync(int id, int cnt) {
    asm volatile("bar.sync %0, %1;" :: "r"(id), "r"(cnt) : "memory");
}

// ---------------- kernel 1: QKV projection ----------------
__global__ void qkv_kernel(const float* __restrict__ x,
                           const float* __restrict__ Wq, const float* __restrict__ bq,
                           const float* __restrict__ Wk, const float* __restrict__ bk,
                           const float* __restrict__ Wv, const float* __restrict__ bv) {
    __shared__ float w[3 * 196 + 3 * 14];
    int tid = threadIdx.x;
    for (int k = tid; k < 196; k += blockDim.x) {
        w[k] = Wq[k]; w[196 + k] = Wk[k]; w[392 + k] = Wv[k];
    }
    if (tid < 14) { w[588 + tid] = bq[tid]; w[602 + tid] = bk[tid]; w[616 + tid] = bv[tid]; }
    __syncthreads();

    int t = blockIdx.x * blockDim.x + tid;          // token index over B*N
    int b = t >> 10, i = t & 1023;
    float xv[14];
#pragma unroll
    for (int f = 0; f < 14; f++) xv[f] = x[(size_t)t * 14 + f];

#pragma unroll
    for (int e = 0; e < 14; e++) {
        float q = w[588 + e], k = w[602 + e], v = w[616 + e];
#pragma unroll
        for (int f = 0; f < 14; f++) {
            q = fmaf(w[e * 14 + f],       xv[f], q);
            k = fmaf(w[196 + e * 14 + f], xv[f], k);
            v = fmaf(w[392 + e * 14 + f], xv[f], v);
        }
        int h = e / 7, eh = e - h * 7;
        size_t idx = (((size_t)b * 2 + h) * N + i) * HDP + eh;
        g_Q[idx] = q; g_K[idx] = k; g_V[idx] = v;
    }
#pragma unroll
    for (int h = 0; h < 2; h++) {
        size_t idx = (((size_t)b * 2 + h) * N + i) * HDP + 7;
        g_Q[idx] = 0.f; g_K[idx] = 0.f; g_V[idx] = 0.f;
    }
}

// ---------------- kernel 2: fused attention (split-head, log2 domain) ----------------
// grid (8, 64), block 256 = 8 warps = 4 pairs. One thread = one (query, head).
__global__ __launch_bounds__(256) void attn_kernel(const float* __restrict__ cert,
                                                   const float* __restrict__ Wo,
                                                   const float* __restrict__ bo,
                                                   float* __restrict__ out,
                                                   float* __restrict__ out_cert) {
    __shared__ float sWo[196];
    __shared__ float sbo[16];
    __shared__ float ph[4][2][32][33];   // [pair][head][query][j]; head0 slab reused for t^10

    int tid = threadIdx.x, w = tid >> 5, lane = tid & 31;
    int pair = w >> 1, h = w & 1;
    for (int k = tid; k < 196; k += 256) sWo[k] = Wo[k];
    if (tid < 14) sbo[tid] = bo[tid];
    __syncthreads();

    int b = blockIdx.y;
    int q = blockIdx.x * 128 + pair * 32 + lane;    // this thread's query row

    const float4* Kh = (const float4*)(g_K + ((size_t)b * 2 + h) * 8192);
    const float4* Vh = (const float4*)(g_V + ((size_t)b * 2 + h) * 8192);
    const float4* Qh = (const float4*)(g_Q + ((size_t)b * 2 + h) * 8192);

    // fold 1/sqrt(7) * log2(e) into q: scores live in log2 domain -> bare EX2
    const float sc = rsqrtf(7.0f) * 1.4426950408889634f;
    float4 qa = Qh[2 * q], qb = Qh[2 * q + 1];
    qa.x *= sc; qa.y *= sc; qa.z *= sc; qa.w *= sc;
    qb.x *= sc; qb.y *= sc; qb.z *= sc; qb.w *= sc;

    // pass 1: softmax denominator for (q, h)
    float Z = 0.f;
#pragma unroll 4
    for (int j = 0; j < 1024; j++)
        Z += exp2f(dot8(qa, Kh[2 * j], qb, Kh[2 * j + 1]));
    float inv = 1.f / Z;

    // pass 2
    float4 va = make_float4(0.f, 0.f, 0.f, 0.f), vb = va;
    float ent2 = 0.f;                               // entropy half, log2 units
    size_t prow_base = ((size_t)b * N + (size_t)blockIdx.x * 128 + pair * 32) * N;
    const int bar = 1 + pair;

    for (int jc = 0; jc < 1024; jc += 32) {
#pragma unroll 4
        for (int jj = 0; jj < 32; jj++) {
            int j = jc + jj;
            float p = exp2f(dot8(qa, Kh[2 * j], qb, Kh[2 * j + 1])) * inv;
            ph[pair][h][lane][jj] = p;
            va = fma4(p, Vh[2 * j], va);
            vb = fma4(p, Vh[2 * j + 1], vb);
        }
        barsync(bar, 64);
#pragma unroll
        for (int k = 0; k < 16; k++) {
            int jj = h * 16 + k;
            float p0 = ph[pair][0][lane][jj];
            float p1 = ph[pair][1][lane][jj];
            float a = 0.5f * (p0 + p1);
            float t = a + SEPS;
            ent2 -= a * __log2f(t);
            float t2 = t * t, t4 = t2 * t2;
            ph[pair][0][lane][jj] = t4 * t4 * t2;   // t^10, overwrites dead p0
        }
        barsync(bar, 64);
#pragma unroll
        for (int r2 = 0; r2 < 16; r2++) {
            int r = h * 16 + r2;
            g_P0[prow_base + (size_t)r * N + jc + lane] = ph[pair][0][r][lane];
        }
        barsync(bar, 64);
    }

    // epilogue: head-1 warp hands its V accums + entropy half to head-0 warp
    float* xch = &ph[pair][1][lane][0];             // ph free after last barrier
    if (h == 1) {
        xch[0] = va.x; xch[1] = va.y; xch[2] = va.z; xch[3] = va.w;
        xch[4] = vb.x; xch[5] = vb.y; xch[6] = vb.z;
        xch[8] = ent2;
    }
    barsync(bar, 64);
    if (h == 0) {
        float pre[14] = {va.x, va.y, va.z, va.w, vb.x, vb.y, vb.z,
                         xch[0], xch[1], xch[2], xch[3], xch[4], xch[5], xch[6]};
        float* orow = out + ((size_t)b * N + q) * 14;
#pragma unroll
        for (int e = 0; e < 14; e++) {
            float o = sbo[e];
#pragma unroll
            for (int f = 0; f < 14; f++) o = fmaf(sWo[e * 14 + f], pre[f], o);
            orow[e] = o;
        }
        float entf = (ent2 + xch[8]) * 0.69314718056f;       // back to nats
        float cu = 1.f / (1.f + __expf(entf - 6.9314718f));  // sigmoid(log1024 - ent)
        out_cert[b * N + q] = fmaxf(cert[b * N + q], cu);
    }
}

// ---------------- Sinkhorn: fused row+col pass + last-block c-update ----------------
// u_i = row_i . c ; r_i <- r_i/(r_i u_i + eps) ; vpart[s] = sum_{i in slab} r'_i P0_ij.
// The LAST finishing block of each batch (per-batch atomic counter) then sums the 64
// vpart slabs in fixed order and writes c' = c/(c v + eps) -- single block, fixed
// order => deterministic; counter reset => graph-replay-safe. No separate cupd kernel.
// grid (NSLAB=64, B=64), block 512 (two 256-thread halves of 8 rows each).
template<bool FIRST>
__global__ __launch_bounds__(512) void sink_fused_kernel() {
    __shared__ float su[16][8];
    __shared__ float sr[16];
    __shared__ float4 stage[256];
    __shared__ int lastFlag;

    int b = blockIdx.y, s = blockIdx.x;
    int tid = threadIdx.x;
    int half = tid >> 8, t8 = tid & 255;
    int w = tid >> 5, lane = tid & 31;

    float4 c4 = FIRST ? make_float4(1.f, 1.f, 1.f, 1.f)
                      : ((const float4*)(g_c + b * 1024))[t8];

    const float4* hb = (const float4*)(g_P0 + ((size_t)b * N + (size_t)s * 16) * N)
                       + (size_t)half * 8 * 256;

    // phase A: row dots (streamed, high MLP)
    float t[8];
#pragma unroll
    for (int i = 0; i < 8; i++) t[i] = dot4(hb[(size_t)i * 256 + t8], c4);
#pragma unroll
    for (int i = 0; i < 8; i++) {
        float acc = t[i];
#pragma unroll
        for (int off = 16; off; off >>= 1) acc += __shfl_xor_sync(0xffffffffu, acc, off);
        if (lane == 0) su[half * 8 + i][w & 7] = acc;
    }
    __syncthreads();
    if (tid < 16) {
        float u = 0.f;
#pragma unroll
        for (int k = 0; k < 8; k++) u += su[tid][k];
        int ri = b * 1024 + s * 16 + tid;
        float r = FIRST ? 1.f : g_r[ri];
        r = r / fmaf(r, u, SEPS);
        g_r[ri] = r;
        sr[tid] = r;
    }
    __syncthreads();

    // phase B: column partials with updated r (reloads hit L1/L2)
    float4 v = make_float4(0.f, 0.f, 0.f, 0.f);
#pragma unroll
    for (int i = 0; i < 8; i++) v = fma4(sr[half * 8 + i], hb[(size_t)i * 256 + t8], v);
    if (half == 1) stage[t8] = v;
    __syncthreads();
    if (half == 0) {
        float4 o = stage[t8];
        v.x += o.x; v.y += o.y; v.z += o.z; v.w += o.w;
        ((float4*)(g_vpart + ((size_t)s * B + b) * N))[t8] = v;
        __threadfence();                 // release our vpart slab device-wide
    }
    __syncthreads();

    // completion: last block of this batch performs the deterministic c-update
    if (tid == 0) {
        int old = atomicAdd(&g_ctr[b], 1);
        lastFlag = (old == NSLAB - 1);
    }
    __syncthreads();
    if (lastFlag) {
        __threadfence();                 // all 64 slabs' vpart now visible
        const float4* vp = (const float4*)g_vpart;
        float4 acc = make_float4(0.f, 0.f, 0.f, 0.f);
#pragma unroll
        for (int k = 0; k < 32; k++) {
            int sl = half * 32 + k;
            acc = add4(acc, vp[((size_t)sl * B + b) * 256 + t8]);
        }
        if (half == 1) stage[t8] = acc;
        __syncthreads();
        if (half == 0) {
            float4 vv = add4(acc, stage[t8]);
            float4 c = FIRST ? make_float4(1.f, 1.f, 1.f, 1.f)
                             : ((const float4*)(g_c + b * 1024))[t8];
            c.x = c.x / fmaf(c.x, vv.x, SEPS);
            c.y = c.y / fmaf(c.y, vv.y, SEPS);
            c.z = c.z / fmaf(c.z, vv.z, SEPS);
            c.w = c.w / fmaf(c.w, vv.w, SEPS);
            ((float4*)(g_c + b * 1024))[t8] = c;
        }
        if (tid == 0) g_ctr[b] = 0;      // replay-safe reset
    }
}

// final: argmax_j P0_ij * c_j (r drops out), gather permutation
__global__ __launch_bounds__(256) void sink_argmax_kernel(const int* __restrict__ perm,
                                                          float* __restrict__ out_perm) {
    int b = blockIdx.y;
    __shared__ float scm[1024];
    for (int idx = threadIdx.x; idx < 1024; idx += 256) scm[idx] = g_c[b * 1024 + idx];
    __syncthreads();
    int w = threadIdx.x >> 5, lane = threadIdx.x & 31;
    int i = blockIdx.x * 8 + w;
    const float4* row4 = (const float4*)(g_P0 + ((size_t)b * N + i) * N);
    const float4* c4s = (const float4*)scm;
    float best = -1.f; int bi = 1024;
#pragma unroll
    for (int k = 0; k < 8; k++) {
        int j4 = lane + 32 * k;
        float4 p = row4[j4], c = c4s[j4];
        float v0 = p.x * c.x, v1 = p.y * c.y, v2 = p.z * c.z, v3 = p.w * c.w;
        if (v0 > best) { best = v0; bi = 4 * j4; }
        if (v1 > best) { best = v1; bi = 4 * j4 + 1; }
        if (v2 > best) { best = v2; bi = 4 * j4 + 2; }
        if (v3 > best) { best = v3; bi = 4 * j4 + 3; }
    }
#pragma unroll
    for (int off = 16; off; off >>= 1) {
        float ov = __shfl_xor_sync(0xffffffffu, best, off);
        int   oi = __shfl_xor_sync(0xffffffffu, bi, off);
        if (ov > best || (ov == best && oi < bi)) { best = ov; bi = oi; }
    }
    if (lane == 0) out_perm[b * 1024 + i] = (float)perm[b * 1024 + bi];
}

// ---------------- launch ----------------
extern "C" void kernel_launch(void* const* d_in, const int* in_sizes, int n_in,
                              void* d_out, int out_size) {
    const float* x    = (const float*)d_in[0];
    const float* cert = (const float*)d_in[1];
    const int*   perm = (const int*)d_in[2];
    const float* Wq = (const float*)d_in[3];  const float* bq = (const float*)d_in[4];
    const float* Wk = (const float*)d_in[5];  const float* bk = (const float*)d_in[6];
    const float* Wv = (const float*)d_in[7];  const float* bv = (const float*)d_in[8];
    const float* Wo = (const float*)d_in[9];  const float* bo = (const float*)d_in[10];

    float* out      = (float*)d_out;                       // (b,n,14)
    float* out_cert = out + (size_t)B * N * D;             // (b,n)
    float* out_perm = out_cert + (size_t)B * N;            // (b,n) as float

    qkv_kernel<<<256, 256>>>(x, Wq, bq, Wk, bk, Wv, bv);
    attn_kernel<<<dim3(8, 64), 256>>>(cert, Wo, bo, out, out_cert);

    // iteration 1 (r=c=1 folded), then 19 more; each launch also produces c for
    // the next via its per-batch last-finishing block.
    sink_fused_kernel<true><<<dim3(NSLAB, 64), 512>>>();
    for (int t = 1; t < 20; t++)
        sink_fused_kernel<false><<<dim3(NSLAB, 64), 512>>>();

    sink_argmax_kernel<<<dim3(128, 64), 256>>>(perm, out_perm);
}

// round 17
// speedup vs baseline: 2.0097x; 1.3057x over previous
#include <cuda_runtime.h>

#define B 64
#define N 1024
#define D 14
#define HDP 8          // head dim padded 7 -> 8
#define SEPS 1e-10f

// ---------------- device scratch (static globals: allowed) ----------------
__device__ float g_P0[(size_t)B * N * N];        // 256 MB: (avg_attn + eps)^10
__device__ float g_Q[B * 2 * N * HDP];           // (b,h,n,8)
__device__ float g_K[B * 2 * N * HDP];
__device__ float g_V[B * 2 * N * HDP];
__device__ float g_cp[2][B * 4 * N];             // per-(batch,ctarank) col partials, dbl-buffered

// ---------------- helpers ----------------
__device__ __forceinline__ float dot8(float4 a, float4 b, float4 c, float4 d) {
    return fmaf(a.x, b.x, fmaf(a.y, b.y, fmaf(a.z, b.z, fmaf(a.w, b.w,
           fmaf(c.x, d.x, fmaf(c.y, d.y, fmaf(c.z, d.z, c.w * d.w)))))));
}
__device__ __forceinline__ float4 fma4(float s, float4 v, float4 acc) {
    acc.x = fmaf(s, v.x, acc.x); acc.y = fmaf(s, v.y, acc.y);
    acc.z = fmaf(s, v.z, acc.z); acc.w = fmaf(s, v.w, acc.w);
    return acc;
}
__device__ __forceinline__ float dot4(float4 a, float4 b) {
    return fmaf(a.x, b.x, fmaf(a.y, b.y, fmaf(a.z, b.z, a.w * b.w)));
}
__device__ __forceinline__ float4 add4(float4 a, float4 b) {
    return make_float4(a.x + b.x, a.y + b.y, a.z + b.z, a.w + b.w);
}
__device__ __forceinline__ void barsync(int id, int cnt) {
    asm volatile("bar.sync %0, %1;" :: "r"(id), "r"(cnt) : "memory");
}

// ---------------- kernel 1: QKV projection ----------------
__global__ void qkv_kernel(const float* __restrict__ x,
                           const float* __restrict__ Wq, const float* __restrict__ bq,
                           const float* __restrict__ Wk, const float* __restrict__ bk,
                           const float* __restrict__ Wv, const float* __restrict__ bv) {
    __shared__ float w[3 * 196 + 3 * 14];
    int tid = threadIdx.x;
    for (int k = tid; k < 196; k += blockDim.x) {
        w[k] = Wq[k]; w[196 + k] = Wk[k]; w[392 + k] = Wv[k];
    }
    if (tid < 14) { w[588 + tid] = bq[tid]; w[602 + tid] = bk[tid]; w[616 + tid] = bv[tid]; }
    __syncthreads();

    int t = blockIdx.x * blockDim.x + tid;          // token index over B*N
    int b = t >> 10, i = t & 1023;
    float xv[14];
#pragma unroll
    for (int f = 0; f < 14; f++) xv[f] = x[(size_t)t * 14 + f];

#pragma unroll
    for (int e = 0; e < 14; e++) {
        float q = w[588 + e], k = w[602 + e], v = w[616 + e];
#pragma unroll
        for (int f = 0; f < 14; f++) {
            q = fmaf(w[e * 14 + f],       xv[f], q);
            k = fmaf(w[196 + e * 14 + f], xv[f], k);
            v = fmaf(w[392 + e * 14 + f], xv[f], v);
        }
        int h = e / 7, eh = e - h * 7;
        size_t idx = (((size_t)b * 2 + h) * N + i) * HDP + eh;
        g_Q[idx] = q; g_K[idx] = k; g_V[idx] = v;
    }
#pragma unroll
    for (int h = 0; h < 2; h++) {
        size_t idx = (((size_t)b * 2 + h) * N + i) * HDP + 7;
        g_Q[idx] = 0.f; g_K[idx] = 0.f; g_V[idx] = 0.f;
    }
}

// ---------------- kernel 2: fused attention (split-head, log2 domain) ----------------
// grid (8, 64), block 256 = 8 warps = 4 pairs. One thread = one (query, head).
__global__ __launch_bounds__(256) void attn_kernel(const float* __restrict__ cert,
                                                   const float* __restrict__ Wo,
                                                   const float* __restrict__ bo,
                                                   float* __restrict__ out,
                                                   float* __restrict__ out_cert) {
    __shared__ float sWo[196];
    __shared__ float sbo[16];
    __shared__ float ph[4][2][32][33];   // [pair][head][query][j]; head0 slab reused for t^10

    int tid = threadIdx.x, w = tid >> 5, lane = tid & 31;
    int pair = w >> 1, h = w & 1;
    for (int k = tid; k < 196; k += 256) sWo[k] = Wo[k];
    if (tid < 14) sbo[tid] = bo[tid];
    __syncthreads();

    int b = blockIdx.y;
    int q = blockIdx.x * 128 + pair * 32 + lane;    // this thread's query row

    const float4* Kh = (const float4*)(g_K + ((size_t)b * 2 + h) * 8192);
    const float4* Vh = (const float4*)(g_V + ((size_t)b * 2 + h) * 8192);
    const float4* Qh = (const float4*)(g_Q + ((size_t)b * 2 + h) * 8192);

    // fold 1/sqrt(7) * log2(e) into q: scores live in log2 domain -> bare EX2
    const float sc = rsqrtf(7.0f) * 1.4426950408889634f;
    float4 qa = Qh[2 * q], qb = Qh[2 * q + 1];
    qa.x *= sc; qa.y *= sc; qa.z *= sc; qa.w *= sc;
    qb.x *= sc; qb.y *= sc; qb.z *= sc; qb.w *= sc;

    // pass 1: softmax denominator for (q, h)
    float Z = 0.f;
#pragma unroll 4
    for (int j = 0; j < 1024; j++)
        Z += exp2f(dot8(qa, Kh[2 * j], qb, Kh[2 * j + 1]));
    float inv = 1.f / Z;

    // pass 2
    float4 va = make_float4(0.f, 0.f, 0.f, 0.f), vb = va;
    float ent2 = 0.f;                               // entropy half, log2 units
    size_t prow_base = ((size_t)b * N + (size_t)blockIdx.x * 128 + pair * 32) * N;
    const int bar = 1 + pair;

    for (int jc = 0; jc < 1024; jc += 32) {
#pragma unroll 4
        for (int jj = 0; jj < 32; jj++) {
            int j = jc + jj;
            float p = exp2f(dot8(qa, Kh[2 * j], qb, Kh[2 * j + 1])) * inv;
            ph[pair][h][lane][jj] = p;
            va = fma4(p, Vh[2 * j], va);
            vb = fma4(p, Vh[2 * j + 1], vb);
        }
        barsync(bar, 64);
#pragma unroll
        for (int k = 0; k < 16; k++) {
            int jj = h * 16 + k;
            float p0 = ph[pair][0][lane][jj];
            float p1 = ph[pair][1][lane][jj];
            float a = 0.5f * (p0 + p1);
            float t = a + SEPS;
            ent2 -= a * __log2f(t);
            float t2 = t * t, t4 = t2 * t2;
            ph[pair][0][lane][jj] = t4 * t4 * t2;   // t^10, overwrites dead p0
        }
        barsync(bar, 64);
#pragma unroll
        for (int r2 = 0; r2 < 16; r2++) {
            int r = h * 16 + r2;
            g_P0[prow_base + (size_t)r * N + jc + lane] = ph[pair][0][r][lane];
        }
        barsync(bar, 64);
    }

    // epilogue: head-1 warp hands its V accums + entropy half to head-0 warp
    float* xch = &ph[pair][1][lane][0];             // ph free after last barrier
    if (h == 1) {
        xch[0] = va.x; xch[1] = va.y; xch[2] = va.z; xch[3] = va.w;
        xch[4] = vb.x; xch[5] = vb.y; xch[6] = vb.z;
        xch[8] = ent2;
    }
    barsync(bar, 64);
    if (h == 0) {
        float pre[14] = {va.x, va.y, va.z, va.w, vb.x, vb.y, vb.z,
                         xch[0], xch[1], xch[2], xch[3], xch[4], xch[5], xch[6]};
        float* orow = out + ((size_t)b * N + q) * 14;
#pragma unroll
        for (int e = 0; e < 14; e++) {
            float o = sbo[e];
#pragma unroll
            for (int f = 0; f < 14; f++) o = fmaf(sWo[e * 14 + f], pre[f], o);
            orow[e] = o;
        }
        float entf = (ent2 + xch[8]) * 0.69314718056f;       // back to nats
        float cu = 1.f / (1.f + __expf(entf - 6.9314718f));  // sigmoid(log1024 - ent)
        out_cert[b * N + q] = fmaxf(cert[b * N + q], cu);
    }
}

// ---------------- Sinkhorn: persistent cluster kernel (all 20 iters + argmax) ----------------
// Cluster (4,1,1) owns one batch; CTA rank owns 256 rows. Per iteration:
//   16 x [R9 slab: row dots vs c (smem), r update (smem, CTA-exclusive), col-partial
//        accumulate in registers with phase-B L1 reload]
//   -> 4 KB col partial to global (double-buffered) -> cluster barrier (one per iter;
//   double buffer makes the second barrier unnecessary) -> each CTA redundantly sums
//   the 4 partials in fixed rank order and updates c in smem (deterministic).
// After iter 20: c_20 computed the same way, then per-CTA argmax over its 256 rows.
__global__ __launch_bounds__(512, 2) __cluster_dims__(4, 1, 1)
void sink_persist_kernel(const int* __restrict__ perm, float* __restrict__ out_perm) {
    __shared__ float4 c_vec[256];    // c for the whole batch (1024 floats)
    __shared__ float  sr_all[256];   // r for this CTA's 256 rows
    __shared__ float  su[16][8];
    __shared__ float  srs[16];
    __shared__ float4 stage[256];

    int b = blockIdx.y;
    int cta = blockIdx.x;            // cluster rank 0..3
    int tid = threadIdx.x;
    int half = tid >> 8, t8 = tid & 255;
    int w = tid >> 5, lane = tid & 31;

    const float4* base0 = (const float4*)(g_P0 + ((size_t)b * N + (size_t)cta * 256) * N);

    for (int t = 1; t <= 20; t++) {
        float4 c4 = (t == 1) ? make_float4(1.f, 1.f, 1.f, 1.f) : c_vec[t8];
        float4 v = make_float4(0.f, 0.f, 0.f, 0.f);

#pragma unroll 1
        for (int sl = 0; sl < 16; sl++) {
            const float4* hb = base0 + ((size_t)sl * 16 + half * 8) * 256;
            // phase A: 8 row dots (streamed, high MLP)
            float tt[8];
#pragma unroll
            for (int i = 0; i < 8; i++) tt[i] = dot4(hb[(size_t)i * 256 + t8], c4);
#pragma unroll
            for (int i = 0; i < 8; i++) {
                float acc = tt[i];
#pragma unroll
                for (int off = 16; off; off >>= 1)
                    acc += __shfl_xor_sync(0xffffffffu, acc, off);
                if (lane == 0) su[half * 8 + i][w & 7] = acc;
            }
            __syncthreads();
            if (tid < 16) {
                float u = 0.f;
#pragma unroll
                for (int k = 0; k < 8; k++) u += su[tid][k];
                float r = (t == 1) ? 1.f : sr_all[sl * 16 + tid];
                r = r / fmaf(r, u, SEPS);
                sr_all[sl * 16 + tid] = r;
                srs[tid] = r;
            }
            __syncthreads();
            // phase B: col partials with updated r (reload hits L1)
#pragma unroll
            for (int i = 0; i < 8; i++)
                v = fma4(srs[half * 8 + i], hb[(size_t)i * 256 + t8], v);
        }

        // combine halves, publish this CTA's 4 KB col partial
        if (half == 1) stage[t8] = v;
        __syncthreads();
        if (half == 0) {
            v = add4(v, stage[t8]);
            ((float4*)(g_cp[t & 1] + ((size_t)(b * 4 + cta)) * N))[t8] = v;
        }
        __threadfence();                              // order publish before barrier release
        asm volatile("barrier.cluster.arrive.aligned;" ::: "memory");
        asm volatile("barrier.cluster.wait.aligned;" ::: "memory");

        // redundant deterministic c-update (fixed rank order 0..3)
        if (half == 0) {
            const float4* vp = (const float4*)(g_cp[t & 1] + (size_t)b * 4 * N);
            float4 s = add4(add4(vp[t8], vp[256 + t8]),
                            add4(vp[512 + t8], vp[768 + t8]));
            float4 c = (t == 1) ? make_float4(1.f, 1.f, 1.f, 1.f) : c_vec[t8];
            c.x = c.x / fmaf(c.x, s.x, SEPS);
            c.y = c.y / fmaf(c.y, s.y, SEPS);
            c.z = c.z / fmaf(c.z, s.z, SEPS);
            c.w = c.w / fmaf(c.w, s.w, SEPS);
            c_vec[t8] = c;
        }
        __syncthreads();
    }

    // argmax over this CTA's rows with c_20 (r drops out of per-row argmax)
    const float* cs = (const float*)c_vec;
#pragma unroll 1
    for (int rr = 0; rr < 16; rr++) {
        int i = cta * 256 + w * 16 + rr;
        const float4* row4 = (const float4*)(g_P0 + ((size_t)b * N + i) * N);
        const float4* c4s = (const float4*)cs;
        float best = -1.f; int bi = 1024;
#pragma unroll
        for (int k = 0; k < 8; k++) {
            int j4 = lane + 32 * k;
            float4 p = row4[j4], c = c4s[j4];
            float v0 = p.x * c.x, v1 = p.y * c.y, v2 = p.z * c.z, v3 = p.w * c.w;
            if (v0 > best) { best = v0; bi = 4 * j4; }
            if (v1 > best) { best = v1; bi = 4 * j4 + 1; }
            if (v2 > best) { best = v2; bi = 4 * j4 + 2; }
            if (v3 > best) { best = v3; bi = 4 * j4 + 3; }
        }
#pragma unroll
        for (int off = 16; off; off >>= 1) {
            float ov = __shfl_xor_sync(0xffffffffu, best, off);
            int   oi = __shfl_xor_sync(0xffffffffu, bi, off);
            if (ov > best || (ov == best && oi < bi)) { best = ov; bi = oi; }
        }
        if (lane == 0) out_perm[b * 1024 + i] = (float)perm[b * 1024 + bi];
    }
}

// ---------------- launch ----------------
extern "C" void kernel_launch(void* const* d_in, const int* in_sizes, int n_in,
                              void* d_out, int out_size) {
    const float* x    = (const float*)d_in[0];
    const float* cert = (const float*)d_in[1];
    const int*   perm = (const int*)d_in[2];
    const float* Wq = (const float*)d_in[3];  const float* bq = (const float*)d_in[4];
    const float* Wk = (const float*)d_in[5];  const float* bk = (const float*)d_in[6];
    const float* Wv = (const float*)d_in[7];  const float* bv = (const float*)d_in[8];
    const float* Wo = (const float*)d_in[9];  const float* bo = (const float*)d_in[10];

    float* out      = (float*)d_out;                       // (b,n,14)
    float* out_cert = out + (size_t)B * N * D;             // (b,n)
    float* out_perm = out_cert + (size_t)B * N;            // (b,n) as float

    qkv_kernel<<<256, 256>>>(x, Wq, bq, Wk, bk, Wv, bv);
    attn_kernel<<<dim3(8, 64), 256>>>(cert, Wo, bo, out, out_cert);
    sink_persist_kernel<<<dim3(4, 64), 512>>>(perm, out_perm);
}